// round 1
// baseline (speedup 1.0000x reference)
#include <cuda_runtime.h>
#include <math.h>

#define B_   8
#define S_   1024
#define D_   768
#define H_   12
#define HD_  64
#define M_   (B_ * S_)     // 8192
#define NQKV (3 * D_)      // 2304

// Scratch (allocation-free: __device__ globals)
__device__ float g_qkv[(size_t)M_ * NQKV];   // [B*S, 3D]
__device__ float g_att[(size_t)M_ * D_];     // [B*S, D] attention output (heads merged)

// ---------------------------------------------------------------------------
// SGEMM: C = A[M,K] @ B[K,N] + bias[N], all row-major.
// Requires M%128==0, N%128==0, K%8==0 (true for all calls here).
// 128x128 blocktile, BK=8, 256 threads, 8x8 per-thread microtile.
// ---------------------------------------------------------------------------
__global__ __launch_bounds__(256) void sgemm_bias(
    const float* __restrict__ A, const float* __restrict__ Bm,
    const float* __restrict__ bias, float* __restrict__ C,
    int M, int N, int K)
{
    const int BM = 128, BN = 128, BK = 8;
    __shared__ float As[BK][BM + 4];   // stored transposed: As[k][m]
    __shared__ float Bs[BK][BN + 4];

    int tid = threadIdx.x;
    int tx = tid & 15;        // 0..15 (N direction)
    int ty = tid >> 4;        // 0..15 (M direction)

    const float* Ab = A + (size_t)blockIdx.y * BM * K;
    const float* Bb = Bm + (size_t)blockIdx.x * BN;

    int arow = tid >> 1;            // 0..127
    int acol = (tid & 1) * 4;       // 0 or 4
    int brow = tid >> 5;            // 0..7
    int bcol = (tid & 31) * 4;      // 0..124

    float acc[8][8];
    #pragma unroll
    for (int i = 0; i < 8; i++)
        #pragma unroll
        for (int j = 0; j < 8; j++) acc[i][j] = 0.f;

    for (int k0 = 0; k0 < K; k0 += BK) {
        float4 av = *(const float4*)(Ab + (size_t)arow * K + k0 + acol);
        As[acol + 0][arow] = av.x;
        As[acol + 1][arow] = av.y;
        As[acol + 2][arow] = av.z;
        As[acol + 3][arow] = av.w;
        float4 bv = *(const float4*)(Bb + (size_t)(k0 + brow) * N + bcol);
        *(float4*)&Bs[brow][bcol] = bv;
        __syncthreads();

        #pragma unroll
        for (int k = 0; k < BK; k++) {
            float ra[8], rb[8];
            *(float4*)&ra[0] = *(const float4*)&As[k][ty * 8];
            *(float4*)&ra[4] = *(const float4*)&As[k][ty * 8 + 4];
            *(float4*)&rb[0] = *(const float4*)&Bs[k][tx * 8];
            *(float4*)&rb[4] = *(const float4*)&Bs[k][tx * 8 + 4];
            #pragma unroll
            for (int i = 0; i < 8; i++)
                #pragma unroll
                for (int j = 0; j < 8; j++)
                    acc[i][j] += ra[i] * rb[j];
        }
        __syncthreads();
    }

    float* Cb = C + (size_t)blockIdx.y * BM * N + (size_t)blockIdx.x * BN;
    #pragma unroll
    for (int i = 0; i < 8; i++) {
        int r = ty * 8 + i;
        #pragma unroll
        for (int j4 = 0; j4 < 8; j4 += 4) {
            float4 bb = *(const float4*)(bias + (size_t)blockIdx.x * BN + tx * 8 + j4);
            float4 o;
            o.x = acc[i][j4 + 0] + bb.x;
            o.y = acc[i][j4 + 1] + bb.y;
            o.z = acc[i][j4 + 2] + bb.z;
            o.w = acc[i][j4 + 3] + bb.w;
            *(float4*)(Cb + (size_t)r * N + tx * 8 + j4) = o;
        }
    }
}

// ---------------------------------------------------------------------------
// Flash-attention (causal) over qkv laid out [B*S, 3D]:
//   Q row (b,h,s) = qkv[(b*S+s)*NQKV + h*64 + d]
//   K: +D_, V: +2*D_
// Block = (q-tile of 64 rows, head h, batch b), 256 threads.
// Thread (tx,ty): score/output microtile rows ty*4..+3, cols tx*4..+3.
// Output written directly into merged-head layout g_att[B*S, D].
// ---------------------------------------------------------------------------
#define QS_STRIDE  68   // float4-friendly pad
#define KT_STRIDE  65   // scalar transposed K, 2-way conflicts max
__global__ __launch_bounds__(256) void attn_kernel(
    const float* __restrict__ qkv, float* __restrict__ out)
{
    extern __shared__ float sm[];
    float (*Qs)[QS_STRIDE]  = (float(*)[QS_STRIDE])(sm);                       // [64][68]
    float (*Kts)[KT_STRIDE] = (float(*)[KT_STRIDE])(sm + 64 * QS_STRIDE);      // [64][65] : Kts[d][j]
    float (*Vs)[QS_STRIDE]  = (float(*)[QS_STRIDE])(sm + 64 * QS_STRIDE + 64 * KT_STRIDE);
    float (*Ps)[QS_STRIDE]  = (float(*)[QS_STRIDE])(sm + 2 * 64 * QS_STRIDE + 64 * KT_STRIDE);

    int qt = blockIdx.x, h = blockIdx.y, b = blockIdx.z;
    int tid = threadIdx.x;
    int tx = tid & 15;    // col group
    int ty = tid >> 4;    // row group
    int q0 = qt * 64;

    const float* base = qkv + (size_t)b * S_ * NQKV + h * HD_;

    // Load Q tile [64 x 64] (float4, conflict-free)
    #pragma unroll
    for (int it = 0; it < 4; ++it) {
        int i = tid + it * 256;
        int r = i >> 4, c = (i & 15) * 4;
        float4 v = *(const float4*)(base + (size_t)(q0 + r) * NQKV + c);
        *(float4*)&Qs[r][c] = v;
    }

    float acc[4][4];
    float m[4], l[4];
    #pragma unroll
    for (int i = 0; i < 4; i++) {
        m[i] = -1e30f; l[i] = 0.f;
        #pragma unroll
        for (int j = 0; j < 4; j++) acc[i][j] = 0.f;
    }

    for (int kt = 0; kt <= qt; ++kt) {
        int k0 = kt * 64;
        __syncthreads();   // prior PV reads done before overwriting K/V
        // Load K (transposed into Kts[d][j]) and V
        #pragma unroll
        for (int it = 0; it < 4; ++it) {
            int i = tid + it * 256;
            int r = i >> 4, c = (i & 15) * 4;
            const float* kr = base + (size_t)(k0 + r) * NQKV + D_ + c;
            float4 kv = *(const float4*)kr;
            Kts[c + 0][r] = kv.x;
            Kts[c + 1][r] = kv.y;
            Kts[c + 2][r] = kv.z;
            Kts[c + 3][r] = kv.w;
            float4 vv = *(const float4*)(kr + D_);
            *(float4*)&Vs[r][c] = vv;
        }
        __syncthreads();

        // Scores: s[i][j] = sum_d Q[ty*4+i][d] * K[tx*4+j][d]
        float s[4][4];
        #pragma unroll
        for (int i = 0; i < 4; i++)
            #pragma unroll
            for (int j = 0; j < 4; j++) s[i][j] = 0.f;

        #pragma unroll 8
        for (int d = 0; d < 64; ++d) {
            float qreg[4], kreg[4];
            #pragma unroll
            for (int i = 0; i < 4; i++) qreg[i] = Qs[ty * 4 + i][d];
            #pragma unroll
            for (int j = 0; j < 4; j++) kreg[j] = Kts[d][tx * 4 + j];
            #pragma unroll
            for (int i = 0; i < 4; i++)
                #pragma unroll
                for (int j = 0; j < 4; j++)
                    s[i][j] += qreg[i] * kreg[j];
        }

        const float scale = 0.125f;   // 1/sqrt(64)
        if (kt == qt) {
            #pragma unroll
            for (int i = 0; i < 4; i++)
                #pragma unroll
                for (int j = 0; j < 4; j++) {
                    int row = ty * 4 + i, col = tx * 4 + j;
                    s[i][j] = (col <= row) ? s[i][j] * scale : -1e30f;
                }
        } else {
            #pragma unroll
            for (int i = 0; i < 4; i++)
                #pragma unroll
                for (int j = 0; j < 4; j++) s[i][j] *= scale;
        }

        // Online softmax per row (rows owned by 16-lane groups sharing ty)
        #pragma unroll
        for (int i = 0; i < 4; i++) {
            float mt = fmaxf(fmaxf(s[i][0], s[i][1]), fmaxf(s[i][2], s[i][3]));
            #pragma unroll
            for (int o = 1; o < 16; o <<= 1)
                mt = fmaxf(mt, __shfl_xor_sync(0xffffffffu, mt, o));
            float mn = fmaxf(m[i], mt);
            float corr = __expf(m[i] - mn);
            m[i] = mn;
            l[i] *= corr;
            #pragma unroll
            for (int j = 0; j < 4; j++) acc[i][j] *= corr;

            float p0 = __expf(s[i][0] - mn);
            float p1 = __expf(s[i][1] - mn);
            float p2 = __expf(s[i][2] - mn);
            float p3 = __expf(s[i][3] - mn);
            float4 p4 = make_float4(p0, p1, p2, p3);
            *(float4*)&Ps[ty * 4 + i][tx * 4] = p4;
            float ls = (p0 + p1) + (p2 + p3);
            #pragma unroll
            for (int o = 1; o < 16; o <<= 1)
                ls += __shfl_xor_sync(0xffffffffu, ls, o);
            l[i] += ls;
        }
        __syncthreads();   // Ps visible to all

        // acc += P @ V : acc[i][c] += sum_j Ps[row][j] * Vs[j][tx*4+c]
        #pragma unroll 8
        for (int j = 0; j < 64; ++j) {
            float pv[4];
            #pragma unroll
            for (int i = 0; i < 4; i++) pv[i] = Ps[ty * 4 + i][j];
            float4 v4 = *(const float4*)&Vs[j][tx * 4];
            #pragma unroll
            for (int i = 0; i < 4; i++) {
                acc[i][0] += pv[i] * v4.x;
                acc[i][1] += pv[i] * v4.y;
                acc[i][2] += pv[i] * v4.z;
                acc[i][3] += pv[i] * v4.w;
            }
        }
    }

    // Write O/l into merged-head layout [B*S, D]
    #pragma unroll
    for (int i = 0; i < 4; i++) {
        float inv = 1.f / l[i];
        int row = b * S_ + q0 + ty * 4 + i;
        float4 o = make_float4(acc[i][0] * inv, acc[i][1] * inv,
                               acc[i][2] * inv, acc[i][3] * inv);
        *(float4*)(out + (size_t)row * D_ + h * HD_ + tx * 4) = o;
    }
}

// ---------------------------------------------------------------------------
extern "C" void kernel_launch(void* const* d_in, const int* in_sizes, int n_in,
                              void* d_out, int out_size)
{
    const float* x     = (const float*)d_in[0];
    const float* Wqkv  = (const float*)d_in[1];
    const float* bqkv  = (const float*)d_in[2];
    const float* Wproj = (const float*)d_in[3];
    const float* bproj = (const float*)d_in[4];
    float* out = (float*)d_out;

    float *qkv, *att;
    cudaGetSymbolAddress((void**)&qkv, g_qkv);
    cudaGetSymbolAddress((void**)&att, g_att);

    const int attn_smem = (2 * 64 * QS_STRIDE + 64 * KT_STRIDE + 64 * QS_STRIDE) * (int)sizeof(float);
    cudaFuncSetAttribute(attn_kernel, cudaFuncAttributeMaxDynamicSharedMemorySize, attn_smem);

    // 1) QKV GEMM: [8192,768] @ [768,2304] + bias
    sgemm_bias<<<dim3(NQKV / 128, M_ / 128), 256>>>(x, Wqkv, bqkv, qkv, M_, NQKV, D_);

    // 2) Fused causal attention -> merged-head [8192,768]
    attn_kernel<<<dim3(S_ / 64, H_, B_), 256, attn_smem>>>(qkv, att);

    // 3) Proj GEMM: [8192,768] @ [768,768] + bias
    sgemm_bias<<<dim3(D_ / 128, M_ / 128), 256>>>(att, Wproj, bproj, out, M_, D_, D_);
}

// round 2
// speedup vs baseline: 1.4695x; 1.4695x over previous
#include <cuda_runtime.h>
#include <cuda_bf16.h>
#include <math.h>
#include <stdint.h>

#define B_   8
#define S_   1024
#define D_   768
#define H_   12
#define HD_  64
#define M_   (B_ * S_)     // 8192
#define NQKV (3 * D_)      // 2304
#define K3_  (3 * D_)      // 2304 (tripled-K for bf16x3 split; K=768 for both GEMMs)

// Scratch (allocation-free: __device__ globals)
__device__ float g_qkv[(size_t)M_ * NQKV];                  // [B*S, 3D]
__device__ float g_att[(size_t)M_ * D_];                    // [B*S, D]
__device__ __nv_bfloat16 g_a3[(size_t)M_ * K3_];            // A3: [M, 3K] = [hi|hi|lo]
__device__ __nv_bfloat16 g_b3[(size_t)NQKV * K3_];          // B3t: [N, 3K] = [hi|lo|hi] (transposed)

// ---------------------------------------------------------------------------
// Conversions for bf16x3 split GEMM
// ---------------------------------------------------------------------------
__global__ __launch_bounds__(256) void conv_a3(const float* __restrict__ A,
                                               __nv_bfloat16* __restrict__ A3,
                                               int total /* = M*768 */)
{
    int idx = blockIdx.x * 256 + threadIdx.x;
    if (idx >= total) return;
    int m = idx / D_;
    int k = idx - m * D_;
    float a = A[idx];
    __nv_bfloat16 hi = __float2bfloat16(a);
    float lo = a - __bfloat162float(hi);
    __nv_bfloat16 lob = __float2bfloat16(lo);
    size_t base = (size_t)m * K3_;
    A3[base + k]          = hi;
    A3[base + D_ + k]     = hi;
    A3[base + 2 * D_ + k] = lob;
}

// B fp32 [K=768][N]  ->  B3t bf16 [N][3K]: [k]=hi, [768+k]=lo, [1536+k]=hi
__global__ __launch_bounds__(256) void conv_b3t(const float* __restrict__ Bm,
                                                __nv_bfloat16* __restrict__ B3t,
                                                int N)
{
    __shared__ float t[32][33];
    int tx = threadIdx.x, ty = threadIdx.y;   // blockDim (32,8)
    int x = blockIdx.x * 32 + tx;             // n
    int y0 = blockIdx.y * 32;                 // k
    #pragma unroll
    for (int j = 0; j < 32; j += 8)
        t[ty + j][tx] = Bm[(size_t)(y0 + ty + j) * N + x];
    __syncthreads();
    #pragma unroll
    for (int j = 0; j < 32; j += 8) {
        int n = blockIdx.x * 32 + ty + j;
        int k = y0 + tx;
        float v = t[tx][ty + j];
        __nv_bfloat16 hi = __float2bfloat16(v);
        float lo = v - __bfloat162float(hi);
        size_t base = (size_t)n * K3_;
        B3t[base + k]          = hi;
        B3t[base + D_ + k]     = __float2bfloat16(lo);
        B3t[base + 2 * D_ + k] = hi;
    }
}

// ---------------------------------------------------------------------------
// bf16 tensor-core GEMM (NT): C[M,N] = A3[M,K3] * B3t[N,K3]^T + bias[N]
// 128x128 block tile, BK=32, 3-stage cp.async pipeline, 256 threads,
// 8 warps in 4(M) x 2(N) grid, warp tile 32x64, mma.m16n8k16 bf16.
// ---------------------------------------------------------------------------
#define BM 128
#define BN 128
#define BKg 32
#define SKA 40                       // bf16 row stride in smem (80B, conflict-free)
#define AS_BYTES (BM * SKA * 2)      // 10240
#define STG_BYTES ((BM + BN) * SKA * 2)  // 20480
#define NSTAGE 3
#define KT_ (K3_ / BKg)              // 72

__device__ __forceinline__ void cp_async16(uint32_t dst, const void* src) {
    asm volatile("cp.async.cg.shared.global [%0], [%1], 16;\n" :: "r"(dst), "l"(src));
}
__device__ __forceinline__ void cp_commit() {
    asm volatile("cp.async.commit_group;\n");
}
__device__ __forceinline__ void cp_wait1() {
    asm volatile("cp.async.wait_group 1;\n" ::: "memory");
}
__device__ __forceinline__ void ldsm4(uint32_t* r, uint32_t addr) {
    asm volatile("ldmatrix.sync.aligned.m8n8.x4.shared.b16 {%0,%1,%2,%3}, [%4];\n"
                 : "=r"(r[0]), "=r"(r[1]), "=r"(r[2]), "=r"(r[3]) : "r"(addr));
}
__device__ __forceinline__ void mma16816(float* d, const uint32_t* a, const uint32_t* b) {
    asm volatile(
        "mma.sync.aligned.m16n8k16.row.col.f32.bf16.bf16.f32 "
        "{%0,%1,%2,%3}, {%4,%5,%6,%7}, {%8,%9}, {%0,%1,%2,%3};\n"
        : "+f"(d[0]), "+f"(d[1]), "+f"(d[2]), "+f"(d[3])
        : "r"(a[0]), "r"(a[1]), "r"(a[2]), "r"(a[3]), "r"(b[0]), "r"(b[1]));
}

__global__ __launch_bounds__(256) void gemm_bf16x3(
    const __nv_bfloat16* __restrict__ A3, const __nv_bfloat16* __restrict__ B3t,
    const float* __restrict__ bias, float* __restrict__ C, int N)
{
    extern __shared__ __nv_bfloat16 smem[];
    uint32_t smem_u32 = (uint32_t)__cvta_generic_to_shared(smem);

    int tid = threadIdx.x;
    int lane = tid & 31, wid = tid >> 5;
    int wm = wid & 3, wn = wid >> 2;          // warp grid 4(M) x 2(N)
    int bm = blockIdx.y * BM, bn = blockIdx.x * BN;

    // ldmatrix per-lane byte offsets (within a stage)
    int q = lane >> 3, r = lane & 7;
    uint32_t offA[2], offB[4];
    #pragma unroll
    for (int mi = 0; mi < 2; mi++) {
        int rowA = wm * 32 + mi * 16 + (q & 1) * 8 + r;
        offA[mi] = (uint32_t)((rowA * SKA + (q >> 1) * 8) * 2);
    }
    #pragma unroll
    for (int nt = 0; nt < 4; nt++) {
        int rowB = wn * 64 + nt * 16 + (q >> 1) * 8 + r;
        offB[nt] = (uint32_t)(AS_BYTES + (rowB * SKA + (q & 1) * 8) * 2);
    }

    float d[2][8][4];
    #pragma unroll
    for (int mi = 0; mi < 2; mi++)
        #pragma unroll
        for (int nj = 0; nj < 8; nj++)
            #pragma unroll
            for (int e = 0; e < 4; e++) d[mi][nj][e] = 0.f;

    // cp.async stage loader: 2 chunks per thread per operand
    int c0row = tid >> 2, c0seg = tid & 3;
    int c1row = (tid + 256) >> 2, c1seg = tid & 3;   // (tid+256)&3 == tid&3

    auto load_stage = [&](int s, int kt) {
        uint32_t base = smem_u32 + (uint32_t)s * STG_BYTES;
        const __nv_bfloat16* sA0 = A3 + (size_t)(bm + c0row) * K3_ + kt * BKg + c0seg * 8;
        cp_async16(base + (uint32_t)((c0row * SKA + c0seg * 8) * 2), sA0);
        const __nv_bfloat16* sA1 = A3 + (size_t)(bm + c1row) * K3_ + kt * BKg + c1seg * 8;
        cp_async16(base + (uint32_t)((c1row * SKA + c1seg * 8) * 2), sA1);
        const __nv_bfloat16* sB0 = B3t + (size_t)(bn + c0row) * K3_ + kt * BKg + c0seg * 8;
        cp_async16(base + AS_BYTES + (uint32_t)((c0row * SKA + c0seg * 8) * 2), sB0);
        const __nv_bfloat16* sB1 = B3t + (size_t)(bn + c1row) * K3_ + kt * BKg + c1seg * 8;
        cp_async16(base + AS_BYTES + (uint32_t)((c1row * SKA + c1seg * 8) * 2), sB1);
    };

    load_stage(0, 0); cp_commit();
    load_stage(1, 1); cp_commit();

    for (int kt = 0; kt < KT_; kt++) {
        cp_wait1();
        __syncthreads();
        if (kt + 2 < KT_) load_stage((kt + 2) % NSTAGE, kt + 2);
        cp_commit();

        uint32_t sbase = smem_u32 + (uint32_t)(kt % NSTAGE) * STG_BYTES;
        #pragma unroll
        for (int kki = 0; kki < 2; kki++) {
            uint32_t kof = (uint32_t)(kki * 16 * 2);
            uint32_t a[2][4], b[4][4];
            ldsm4(a[0], sbase + offA[0] + kof);
            ldsm4(a[1], sbase + offA[1] + kof);
            ldsm4(b[0], sbase + offB[0] + kof);
            ldsm4(b[1], sbase + offB[1] + kof);
            ldsm4(b[2], sbase + offB[2] + kof);
            ldsm4(b[3], sbase + offB[3] + kof);
            #pragma unroll
            for (int mi = 0; mi < 2; mi++)
                #pragma unroll
                for (int nt = 0; nt < 4; nt++) {
                    mma16816(d[mi][nt * 2],     a[mi], &b[nt][0]);
                    mma16816(d[mi][nt * 2 + 1], a[mi], &b[nt][2]);
                }
        }
    }

    // Epilogue
    #pragma unroll
    for (int mi = 0; mi < 2; mi++) {
        int row = bm + wm * 32 + mi * 16 + (lane >> 2);
        #pragma unroll
        for (int nj = 0; nj < 8; nj++) {
            int col = bn + wn * 64 + nj * 8 + (lane & 3) * 2;
            float2 bb = *(const float2*)(bias + col);
            float2 o0 = make_float2(d[mi][nj][0] + bb.x, d[mi][nj][1] + bb.y);
            *(float2*)(C + (size_t)row * N + col) = o0;
            float2 o1 = make_float2(d[mi][nj][2] + bb.x, d[mi][nj][3] + bb.y);
            *(float2*)(C + (size_t)(row + 8) * N + col) = o1;
        }
    }
}

// ---------------------------------------------------------------------------
// Flash-attention (causal), unchanged from round 1.
// ---------------------------------------------------------------------------
#define QS_STRIDE  68
#define KT_STRIDE  65
__global__ __launch_bounds__(256) void attn_kernel(
    const float* __restrict__ qkv, float* __restrict__ out)
{
    extern __shared__ float sm[];
    float (*Qs)[QS_STRIDE]  = (float(*)[QS_STRIDE])(sm);
    float (*Kts)[KT_STRIDE] = (float(*)[KT_STRIDE])(sm + 64 * QS_STRIDE);
    float (*Vs)[QS_STRIDE]  = (float(*)[QS_STRIDE])(sm + 64 * QS_STRIDE + 64 * KT_STRIDE);
    float (*Ps)[QS_STRIDE]  = (float(*)[QS_STRIDE])(sm + 2 * 64 * QS_STRIDE + 64 * KT_STRIDE);

    int qt = blockIdx.x, h = blockIdx.y, b = blockIdx.z;
    int tid = threadIdx.x;
    int tx = tid & 15;
    int ty = tid >> 4;
    int q0 = qt * 64;

    const float* base = qkv + (size_t)b * S_ * NQKV + h * HD_;

    #pragma unroll
    for (int it = 0; it < 4; ++it) {
        int i = tid + it * 256;
        int rr = i >> 4, cc = (i & 15) * 4;
        float4 v = *(const float4*)(base + (size_t)(q0 + rr) * NQKV + cc);
        *(float4*)&Qs[rr][cc] = v;
    }

    float acc[4][4];
    float m[4], l[4];
    #pragma unroll
    for (int i = 0; i < 4; i++) {
        m[i] = -1e30f; l[i] = 0.f;
        #pragma unroll
        for (int j = 0; j < 4; j++) acc[i][j] = 0.f;
    }

    for (int kt = 0; kt <= qt; ++kt) {
        int k0 = kt * 64;
        __syncthreads();
        #pragma unroll
        for (int it = 0; it < 4; ++it) {
            int i = tid + it * 256;
            int rr = i >> 4, cc = (i & 15) * 4;
            const float* kr = base + (size_t)(k0 + rr) * NQKV + D_ + cc;
            float4 kv = *(const float4*)kr;
            Kts[cc + 0][rr] = kv.x;
            Kts[cc + 1][rr] = kv.y;
            Kts[cc + 2][rr] = kv.z;
            Kts[cc + 3][rr] = kv.w;
            float4 vv = *(const float4*)(kr + D_);
            *(float4*)&Vs[rr][cc] = vv;
        }
        __syncthreads();

        float s[4][4];
        #pragma unroll
        for (int i = 0; i < 4; i++)
            #pragma unroll
            for (int j = 0; j < 4; j++) s[i][j] = 0.f;

        #pragma unroll 8
        for (int dd = 0; dd < 64; ++dd) {
            float qreg[4], kreg[4];
            #pragma unroll
            for (int i = 0; i < 4; i++) qreg[i] = Qs[ty * 4 + i][dd];
            #pragma unroll
            for (int j = 0; j < 4; j++) kreg[j] = Kts[dd][tx * 4 + j];
            #pragma unroll
            for (int i = 0; i < 4; i++)
                #pragma unroll
                for (int j = 0; j < 4; j++)
                    s[i][j] += qreg[i] * kreg[j];
        }

        const float scale = 0.125f;
        if (kt == qt) {
            #pragma unroll
            for (int i = 0; i < 4; i++)
                #pragma unroll
                for (int j = 0; j < 4; j++) {
                    int row = ty * 4 + i, col = tx * 4 + j;
                    s[i][j] = (col <= row) ? s[i][j] * scale : -1e30f;
                }
        } else {
            #pragma unroll
            for (int i = 0; i < 4; i++)
                #pragma unroll
                for (int j = 0; j < 4; j++) s[i][j] *= scale;
        }

        #pragma unroll
        for (int i = 0; i < 4; i++) {
            float mt = fmaxf(fmaxf(s[i][0], s[i][1]), fmaxf(s[i][2], s[i][3]));
            #pragma unroll
            for (int o = 1; o < 16; o <<= 1)
                mt = fmaxf(mt, __shfl_xor_sync(0xffffffffu, mt, o));
            float mn = fmaxf(m[i], mt);
            float corr = __expf(m[i] - mn);
            m[i] = mn;
            l[i] *= corr;
            #pragma unroll
            for (int j = 0; j < 4; j++) acc[i][j] *= corr;

            float p0 = __expf(s[i][0] - mn);
            float p1 = __expf(s[i][1] - mn);
            float p2 = __expf(s[i][2] - mn);
            float p3 = __expf(s[i][3] - mn);
            float4 p4 = make_float4(p0, p1, p2, p3);
            *(float4*)&Ps[ty * 4 + i][tx * 4] = p4;
            float ls = (p0 + p1) + (p2 + p3);
            #pragma unroll
            for (int o = 1; o < 16; o <<= 1)
                ls += __shfl_xor_sync(0xffffffffu, ls, o);
            l[i] += ls;
        }
        __syncthreads();

        #pragma unroll 8
        for (int j = 0; j < 64; ++j) {
            float pv[4];
            #pragma unroll
            for (int i = 0; i < 4; i++) pv[i] = Ps[ty * 4 + i][j];
            float4 v4 = *(const float4*)&Vs[j][tx * 4];
            #pragma unroll
            for (int i = 0; i < 4; i++) {
                acc[i][0] += pv[i] * v4.x;
                acc[i][1] += pv[i] * v4.y;
                acc[i][2] += pv[i] * v4.z;
                acc[i][3] += pv[i] * v4.w;
            }
        }
    }

    #pragma unroll
    for (int i = 0; i < 4; i++) {
        float inv = 1.f / l[i];
        int row = b * S_ + q0 + ty * 4 + i;
        float4 o = make_float4(acc[i][0] * inv, acc[i][1] * inv,
                               acc[i][2] * inv, acc[i][3] * inv);
        *(float4*)(out + (size_t)row * D_ + h * HD_ + tx * 4) = o;
    }
}

// ---------------------------------------------------------------------------
extern "C" void kernel_launch(void* const* d_in, const int* in_sizes, int n_in,
                              void* d_out, int out_size)
{
    const float* x     = (const float*)d_in[0];
    const float* Wqkv  = (const float*)d_in[1];
    const float* bqkv  = (const float*)d_in[2];
    const float* Wproj = (const float*)d_in[3];
    const float* bproj = (const float*)d_in[4];
    float* out = (float*)d_out;

    float *qkv, *att;
    __nv_bfloat16 *a3, *b3;
    cudaGetSymbolAddress((void**)&qkv, g_qkv);
    cudaGetSymbolAddress((void**)&att, g_att);
    cudaGetSymbolAddress((void**)&a3, g_a3);
    cudaGetSymbolAddress((void**)&b3, g_b3);

    const int gemm_smem = NSTAGE * STG_BYTES;   // 61440
    cudaFuncSetAttribute(gemm_bf16x3, cudaFuncAttributeMaxDynamicSharedMemorySize, gemm_smem);
    const int attn_smem = (2 * 64 * QS_STRIDE + 64 * KT_STRIDE + 64 * QS_STRIDE) * (int)sizeof(float);
    cudaFuncSetAttribute(attn_kernel, cudaFuncAttributeMaxDynamicSharedMemorySize, attn_smem);

    const int convA_total = M_ * D_;

    // 1) QKV = x @ Wqkv + bqkv  (bf16x3 tensor GEMM)
    conv_a3<<<(convA_total + 255) / 256, 256>>>(x, a3, convA_total);
    conv_b3t<<<dim3(NQKV / 32, D_ / 32), dim3(32, 8)>>>(Wqkv, b3, NQKV);
    gemm_bf16x3<<<dim3(NQKV / BN, M_ / BM), 256, gemm_smem>>>(a3, b3, bqkv, qkv, NQKV);

    // 2) Fused causal attention
    attn_kernel<<<dim3(S_ / 64, H_, B_), 256, attn_smem>>>(qkv, att);

    // 3) out = att @ Wproj + bproj
    conv_a3<<<(convA_total + 255) / 256, 256>>>(att, a3, convA_total);
    conv_b3t<<<dim3(D_ / 32, D_ / 32), dim3(32, 8)>>>(Wproj, b3, D_);
    gemm_bf16x3<<<dim3(D_ / BN, M_ / BM), 256, gemm_smem>>>(a3, b3, bproj, out, D_);
}

// round 3
// speedup vs baseline: 2.1611x; 1.4706x over previous
#include <cuda_runtime.h>
#include <cuda_bf16.h>
#include <math.h>
#include <stdint.h>

#define B_   8
#define S_   1024
#define D_   768
#define H_   12
#define HD_  64
#define M_   (B_ * S_)     // 8192
#define NQKV (3 * D_)      // 2304
#define K3_  (3 * D_)      // 2304

// Scratch (allocation-free: __device__ globals)
__device__ __nv_bfloat16 g_a3[(size_t)M_ * K3_];      // A3: [M, 3K] = [hi|hi|lo]
__device__ __nv_bfloat16 g_b3[(size_t)NQKV * K3_];    // B3t: [N, 3K] = [hi|lo|hi]
__device__ __nv_bfloat16 g_kv_hi[(size_t)M_ * NQKV];  // qkv hi
__device__ __nv_bfloat16 g_kv_lo[(size_t)M_ * NQKV];  // qkv lo

// ---------------------------------------------------------------------------
// Conversions
// ---------------------------------------------------------------------------
__global__ __launch_bounds__(256) void conv_a3(const float* __restrict__ A,
                                               __nv_bfloat16* __restrict__ A3,
                                               int total)
{
    int idx = blockIdx.x * 256 + threadIdx.x;
    if (idx >= total) return;
    int m = idx / D_;
    int k = idx - m * D_;
    float a = A[idx];
    __nv_bfloat16 hi = __float2bfloat16(a);
    float lo = a - __bfloat162float(hi);
    size_t base = (size_t)m * K3_;
    A3[base + k]          = hi;
    A3[base + D_ + k]     = hi;
    A3[base + 2 * D_ + k] = __float2bfloat16(lo);
}

__global__ __launch_bounds__(256) void conv_b3t(const float* __restrict__ Bm,
                                                __nv_bfloat16* __restrict__ B3t,
                                                int N)
{
    __shared__ float t[32][33];
    int tx = threadIdx.x, ty = threadIdx.y;
    int x = blockIdx.x * 32 + tx;
    int y0 = blockIdx.y * 32;
    #pragma unroll
    for (int j = 0; j < 32; j += 8)
        t[ty + j][tx] = Bm[(size_t)(y0 + ty + j) * N + x];
    __syncthreads();
    #pragma unroll
    for (int j = 0; j < 32; j += 8) {
        int n = blockIdx.x * 32 + ty + j;
        int k = y0 + tx;
        float v = t[tx][ty + j];
        __nv_bfloat16 hi = __float2bfloat16(v);
        float lo = v - __bfloat162float(hi);
        size_t base = (size_t)n * K3_;
        B3t[base + k]          = hi;
        B3t[base + D_ + k]     = __float2bfloat16(lo);
        B3t[base + 2 * D_ + k] = hi;
    }
}

// ---------------------------------------------------------------------------
// PTX helpers
// ---------------------------------------------------------------------------
__device__ __forceinline__ void cp_async16(uint32_t dst, const void* src) {
    asm volatile("cp.async.cg.shared.global [%0], [%1], 16;\n" :: "r"(dst), "l"(src));
}
__device__ __forceinline__ void cp_commit() {
    asm volatile("cp.async.commit_group;\n");
}
__device__ __forceinline__ void cp_wait1() {
    asm volatile("cp.async.wait_group 1;\n" ::: "memory");
}
__device__ __forceinline__ void cp_wait0() {
    asm volatile("cp.async.wait_group 0;\n" ::: "memory");
}
__device__ __forceinline__ void ldsm4(uint32_t* r, uint32_t addr) {
    asm volatile("ldmatrix.sync.aligned.m8n8.x4.shared.b16 {%0,%1,%2,%3}, [%4];\n"
                 : "=r"(r[0]), "=r"(r[1]), "=r"(r[2]), "=r"(r[3]) : "r"(addr));
}
__device__ __forceinline__ void ldsm4t(uint32_t* r, uint32_t addr) {
    asm volatile("ldmatrix.sync.aligned.m8n8.x4.trans.shared.b16 {%0,%1,%2,%3}, [%4];\n"
                 : "=r"(r[0]), "=r"(r[1]), "=r"(r[2]), "=r"(r[3]) : "r"(addr));
}
__device__ __forceinline__ void mma16816(float* d, const uint32_t* a, uint32_t b0, uint32_t b1) {
    asm volatile(
        "mma.sync.aligned.m16n8k16.row.col.f32.bf16.bf16.f32 "
        "{%0,%1,%2,%3}, {%4,%5,%6,%7}, {%8,%9}, {%0,%1,%2,%3};\n"
        : "+f"(d[0]), "+f"(d[1]), "+f"(d[2]), "+f"(d[3])
        : "r"(a[0]), "r"(a[1]), "r"(a[2]), "r"(a[3]), "r"(b0), "r"(b1));
}
__device__ __forceinline__ uint32_t packbf(float a, float b) {
    __nv_bfloat162 h = __floats2bfloat162_rn(a, b);
    return *(uint32_t*)&h;
}

// ---------------------------------------------------------------------------
// bf16 tensor-core GEMM (NT): C = A3[M,K3] * B3t[N,K3]^T + bias
// Epilogue: fp32 (Cf) or bf16 hi/lo split (Chi/Clo).
// ---------------------------------------------------------------------------
#define BM 128
#define BN 128
#define BKg 32
#define SKA 40
#define AS_BYTES (BM * SKA * 2)
#define STG_BYTES ((BM + BN) * SKA * 2)
#define NSTAGE 3
#define KTILES (K3_ / BKg)   // 72

__global__ __launch_bounds__(256) void gemm_bf16x3(
    const __nv_bfloat16* __restrict__ A3, const __nv_bfloat16* __restrict__ B3t,
    const float* __restrict__ bias, float* __restrict__ Cf,
    __nv_bfloat16* __restrict__ Chi, __nv_bfloat16* __restrict__ Clo, int N)
{
    extern __shared__ __nv_bfloat16 smem[];
    uint32_t smem_u32 = (uint32_t)__cvta_generic_to_shared(smem);

    int tid = threadIdx.x;
    int lane = tid & 31, wid = tid >> 5;
    int wm = wid & 3, wn = wid >> 2;
    int bm = blockIdx.y * BM, bn = blockIdx.x * BN;

    int q = lane >> 3, r = lane & 7;
    uint32_t offA[2], offB[4];
    #pragma unroll
    for (int mi = 0; mi < 2; mi++) {
        int rowA = wm * 32 + mi * 16 + (q & 1) * 8 + r;
        offA[mi] = (uint32_t)((rowA * SKA + (q >> 1) * 8) * 2);
    }
    #pragma unroll
    for (int nt = 0; nt < 4; nt++) {
        int rowB = wn * 64 + nt * 16 + (q >> 1) * 8 + r;
        offB[nt] = (uint32_t)(AS_BYTES + (rowB * SKA + (q & 1) * 8) * 2);
    }

    float d[2][8][4];
    #pragma unroll
    for (int mi = 0; mi < 2; mi++)
        #pragma unroll
        for (int nj = 0; nj < 8; nj++)
            #pragma unroll
            for (int e = 0; e < 4; e++) d[mi][nj][e] = 0.f;

    int c0row = tid >> 2, c0seg = tid & 3;
    int c1row = (tid + 256) >> 2;

    auto load_stage = [&](int s, int kt) {
        uint32_t base = smem_u32 + (uint32_t)s * STG_BYTES;
        cp_async16(base + (uint32_t)((c0row * SKA + c0seg * 8) * 2),
                   A3 + (size_t)(bm + c0row) * K3_ + kt * BKg + c0seg * 8);
        cp_async16(base + (uint32_t)((c1row * SKA + c0seg * 8) * 2),
                   A3 + (size_t)(bm + c1row) * K3_ + kt * BKg + c0seg * 8);
        cp_async16(base + AS_BYTES + (uint32_t)((c0row * SKA + c0seg * 8) * 2),
                   B3t + (size_t)(bn + c0row) * K3_ + kt * BKg + c0seg * 8);
        cp_async16(base + AS_BYTES + (uint32_t)((c1row * SKA + c0seg * 8) * 2),
                   B3t + (size_t)(bn + c1row) * K3_ + kt * BKg + c0seg * 8);
    };

    load_stage(0, 0); cp_commit();
    load_stage(1, 1); cp_commit();

    for (int kt = 0; kt < KTILES; kt++) {
        cp_wait1();
        __syncthreads();
        if (kt + 2 < KTILES) load_stage((kt + 2) % NSTAGE, kt + 2);
        cp_commit();

        uint32_t sbase = smem_u32 + (uint32_t)(kt % NSTAGE) * STG_BYTES;
        #pragma unroll
        for (int kki = 0; kki < 2; kki++) {
            uint32_t kof = (uint32_t)(kki * 16 * 2);
            uint32_t a[2][4], b[4][4];
            ldsm4(a[0], sbase + offA[0] + kof);
            ldsm4(a[1], sbase + offA[1] + kof);
            ldsm4(b[0], sbase + offB[0] + kof);
            ldsm4(b[1], sbase + offB[1] + kof);
            ldsm4(b[2], sbase + offB[2] + kof);
            ldsm4(b[3], sbase + offB[3] + kof);
            #pragma unroll
            for (int mi = 0; mi < 2; mi++)
                #pragma unroll
                for (int nt = 0; nt < 4; nt++) {
                    mma16816(d[mi][nt * 2],     a[mi], b[nt][0], b[nt][1]);
                    mma16816(d[mi][nt * 2 + 1], a[mi], b[nt][2], b[nt][3]);
                }
        }
    }

    #pragma unroll
    for (int mi = 0; mi < 2; mi++) {
        int row = bm + wm * 32 + mi * 16 + (lane >> 2);
        #pragma unroll
        for (int nj = 0; nj < 8; nj++) {
            int col = bn + wn * 64 + nj * 8 + (lane & 3) * 2;
            float2 bb = *(const float2*)(bias + col);
            float v00 = d[mi][nj][0] + bb.x, v01 = d[mi][nj][1] + bb.y;
            float v10 = d[mi][nj][2] + bb.x, v11 = d[mi][nj][3] + bb.y;
            if (Cf) {
                *(float2*)(Cf + (size_t)row * N + col) = make_float2(v00, v01);
                *(float2*)(Cf + (size_t)(row + 8) * N + col) = make_float2(v10, v11);
            } else {
                __nv_bfloat16 h00 = __float2bfloat16(v00), h01 = __float2bfloat16(v01);
                __nv_bfloat16 h10 = __float2bfloat16(v10), h11 = __float2bfloat16(v11);
                uint32_t hp0 = packbf(__bfloat162float(h00), 0.f); // placeholder avoided below
                (void)hp0;
                *(uint32_t*)(Chi + (size_t)row * N + col) = ((uint32_t)*(uint16_t*)&h01 << 16) | *(uint16_t*)&h00;
                *(uint32_t*)(Chi + (size_t)(row + 8) * N + col) = ((uint32_t)*(uint16_t*)&h11 << 16) | *(uint16_t*)&h10;
                __nv_bfloat16 l00 = __float2bfloat16(v00 - __bfloat162float(h00));
                __nv_bfloat16 l01 = __float2bfloat16(v01 - __bfloat162float(h01));
                __nv_bfloat16 l10 = __float2bfloat16(v10 - __bfloat162float(h10));
                __nv_bfloat16 l11 = __float2bfloat16(v11 - __bfloat162float(h11));
                *(uint32_t*)(Clo + (size_t)row * N + col) = ((uint32_t)*(uint16_t*)&l01 << 16) | *(uint16_t*)&l00;
                *(uint32_t*)(Clo + (size_t)(row + 8) * N + col) = ((uint32_t)*(uint16_t*)&l11 << 16) | *(uint16_t*)&l10;
            }
        }
    }
}

// ---------------------------------------------------------------------------
// Tensor-core flash attention (causal), bf16 hi/lo split, q-tile 128.
// 8 warps x 16 rows. K/V double-buffered in smem. P stays in registers.
// Output written in proj-GEMM A3 layout [hi|hi|lo].
// ---------------------------------------------------------------------------
#define AST 72                       // smem row stride (bf16 elems)
#define TEN (128 * AST)              // elems per tensor buffer

__global__ __launch_bounds__(256) void attn_mma(
    const __nv_bfloat16* __restrict__ qh, const __nv_bfloat16* __restrict__ ql,
    __nv_bfloat16* __restrict__ a3out)
{
    extern __shared__ __nv_bfloat16 asmem[];
    uint32_t sbase = (uint32_t)__cvta_generic_to_shared(asmem);

    int qt = blockIdx.x, h = blockIdx.y, b = blockIdx.z;
    int tid = threadIdx.x, lane = tid & 31, w = tid >> 5;
    int g = lane >> 2, qr = (lane & 3) * 2;
    int q0 = qt * 128;
    size_t rowbase = (size_t)b * S_;

    // ---- Q fragments (registers, whole kernel) ----
    uint32_t qaH[4][4], qaL[4][4];
    {
        size_t r0 = (rowbase + q0 + w * 16 + g) * NQKV + h * HD_;
        size_t r1 = r0 + (size_t)8 * NQKV;
        #pragma unroll
        for (int kk = 0; kk < 4; kk++) {
            int c = kk * 16 + qr;
            qaH[kk][0] = *(const uint32_t*)(qh + r0 + c);
            qaH[kk][1] = *(const uint32_t*)(qh + r1 + c);
            qaH[kk][2] = *(const uint32_t*)(qh + r0 + c + 8);
            qaH[kk][3] = *(const uint32_t*)(qh + r1 + c + 8);
            qaL[kk][0] = *(const uint32_t*)(ql + r0 + c);
            qaL[kk][1] = *(const uint32_t*)(ql + r1 + c);
            qaL[kk][2] = *(const uint32_t*)(ql + r0 + c + 8);
            qaL[kk][3] = *(const uint32_t*)(ql + r1 + c + 8);
        }
    }

    auto load_tile = [&](int bufsel, int kt) {
        uint32_t sb = sbase + (uint32_t)bufsel * 4 * TEN * 2;
        int k0 = kt * 128;
        #pragma unroll
        for (int j = 0; j < 4; j++) {
            int chunk = tid + j * 256;
            int row = chunk >> 3, c8 = (chunk & 7) * 8;
            size_t grow = (rowbase + k0 + row) * NQKV + h * HD_;
            uint32_t so = (uint32_t)((row * AST + c8) * 2);
            cp_async16(sb + so,               qh + grow + D_ + c8);       // Kh
            cp_async16(sb + TEN * 2 + so,     ql + grow + D_ + c8);       // Kl
            cp_async16(sb + 2 * TEN * 2 + so, qh + grow + 2 * D_ + c8);   // Vh
            cp_async16(sb + 3 * TEN * 2 + so, ql + grow + 2 * D_ + c8);   // Vl
        }
    };

    float o[8][4];
    #pragma unroll
    for (int t = 0; t < 8; t++)
        #pragma unroll
        for (int e = 0; e < 4; e++) o[t][e] = 0.f;
    float m0 = -1e30f, m1 = -1e30f, l0 = 0.f, l1 = 0.f;
    const float sc = 0.125f;

    load_tile(0, 0); cp_commit();

    for (int kt = 0; kt <= qt; kt++) {
        __syncthreads();                 // all warps done with buffer being reloaded
        if (kt < qt) { load_tile((kt + 1) & 1, kt + 1); cp_commit(); cp_wait1(); }
        else cp_wait0();
        __syncthreads();

        uint32_t kb = sbase + (uint32_t)(kt & 1) * 4 * TEN * 2;

        // ---- S = Q K^T (hi/lo split) ----
        float s[16][4];
        #pragma unroll
        for (int t = 0; t < 16; t++)
            #pragma unroll
            for (int e = 0; e < 4; e++) s[t][e] = 0.f;

        int lrow = lane & 15, lseg = (lane >> 4) * 8;
        #pragma unroll
        for (int kk = 0; kk < 4; kk++) {
            #pragma unroll
            for (int np = 0; np < 8; np++) {
                uint32_t addr = kb + (uint32_t)(((np * 16 + lrow) * AST + kk * 16 + lseg) * 2);
                uint32_t bh[4], bl[4];
                ldsm4(bh, addr);
                ldsm4(bl, addr + TEN * 2);
                mma16816(s[2 * np],     qaH[kk], bh[0], bh[2]);
                mma16816(s[2 * np],     qaH[kk], bl[0], bl[2]);
                mma16816(s[2 * np],     qaL[kk], bh[0], bh[2]);
                mma16816(s[2 * np + 1], qaH[kk], bh[1], bh[3]);
                mma16816(s[2 * np + 1], qaH[kk], bl[1], bl[3]);
                mma16816(s[2 * np + 1], qaL[kk], bh[1], bh[3]);
            }
        }

        // ---- causal mask on diagonal tile ----
        if (kt == qt) {
            int rl0 = w * 16 + g, rl1 = rl0 + 8;
            #pragma unroll
            for (int t = 0; t < 16; t++) {
                #pragma unroll
                for (int e = 0; e < 2; e++) {
                    int col = t * 8 + qr + e;
                    if (col > rl0) s[t][e]     = -1e30f;
                    if (col > rl1) s[t][2 + e] = -1e30f;
                }
            }
        }

        // ---- online softmax ----
        float mx0 = -1e30f, mx1 = -1e30f;
        #pragma unroll
        for (int t = 0; t < 16; t++) {
            mx0 = fmaxf(mx0, fmaxf(s[t][0], s[t][1]));
            mx1 = fmaxf(mx1, fmaxf(s[t][2], s[t][3]));
        }
        #pragma unroll
        for (int off = 1; off < 4; off <<= 1) {
            mx0 = fmaxf(mx0, __shfl_xor_sync(0xffffffffu, mx0, off));
            mx1 = fmaxf(mx1, __shfl_xor_sync(0xffffffffu, mx1, off));
        }
        float mn0 = fmaxf(m0, mx0), mn1 = fmaxf(m1, mx1);
        float c0 = __expf(sc * (m0 - mn0)), c1 = __expf(sc * (m1 - mn1));
        m0 = mn0; m1 = mn1;
        l0 *= c0; l1 *= c1;
        #pragma unroll
        for (int t = 0; t < 8; t++) {
            o[t][0] *= c0; o[t][1] *= c0; o[t][2] *= c1; o[t][3] *= c1;
        }
        float sum0 = 0.f, sum1 = 0.f;
        #pragma unroll
        for (int t = 0; t < 16; t++) {
            s[t][0] = __expf(sc * (s[t][0] - mn0));
            s[t][1] = __expf(sc * (s[t][1] - mn0));
            s[t][2] = __expf(sc * (s[t][2] - mn1));
            s[t][3] = __expf(sc * (s[t][3] - mn1));
            sum0 += s[t][0] + s[t][1];
            sum1 += s[t][2] + s[t][3];
        }
        #pragma unroll
        for (int off = 1; off < 4; off <<= 1) {
            sum0 += __shfl_xor_sync(0xffffffffu, sum0, off);
            sum1 += __shfl_xor_sync(0xffffffffu, sum1, off);
        }
        l0 += sum0; l1 += sum1;

        // ---- O += P V (hi/lo split, P from registers) ----
        uint32_t vb = kb + 2 * TEN * 2;
        #pragma unroll
        for (int ks = 0; ks < 8; ks++) {
            int t0 = 2 * ks, t1 = t0 + 1;
            uint32_t aH[4], aL[4];
            float ph[8], pl[8];
            ph[0] = s[t0][0]; ph[1] = s[t0][1]; ph[2] = s[t0][2]; ph[3] = s[t0][3];
            ph[4] = s[t1][0]; ph[5] = s[t1][1]; ph[6] = s[t1][2]; ph[7] = s[t1][3];
            #pragma unroll
            for (int e = 0; e < 8; e++) {
                float hi = __bfloat162float(__float2bfloat16(ph[e]));
                pl[e] = ph[e] - hi;
                ph[e] = hi;
            }
            aH[0] = packbf(ph[0], ph[1]); aH[1] = packbf(ph[2], ph[3]);
            aH[2] = packbf(ph[4], ph[5]); aH[3] = packbf(ph[6], ph[7]);
            aL[0] = packbf(pl[0], pl[1]); aL[1] = packbf(pl[2], pl[3]);
            aL[2] = packbf(pl[4], pl[5]); aL[3] = packbf(pl[6], pl[7]);

            #pragma unroll
            for (int nd = 0; nd < 4; nd++) {
                uint32_t addr = vb + (uint32_t)(((ks * 16 + lrow) * AST + nd * 16 + lseg) * 2);
                uint32_t vh[4], vl[4];
                ldsm4t(vh, addr);
                ldsm4t(vl, addr + TEN * 2);
                mma16816(o[2 * nd],     aH, vh[0], vh[1]);
                mma16816(o[2 * nd],     aH, vl[0], vl[1]);
                mma16816(o[2 * nd],     aL, vh[0], vh[1]);
                mma16816(o[2 * nd + 1], aH, vh[2], vh[3]);
                mma16816(o[2 * nd + 1], aH, vl[2], vl[3]);
                mma16816(o[2 * nd + 1], aL, vh[2], vh[3]);
            }
        }
    }

    // ---- epilogue: write O/l into A3 layout [hi|hi|lo] ----
    float inv0 = 1.f / l0, inv1 = 1.f / l1;
    size_t row0 = (rowbase + q0 + w * 16 + g) * (size_t)K3_;
    size_t row1 = row0 + (size_t)8 * K3_;
    #pragma unroll
    for (int t = 0; t < 8; t++) {
        int col = h * HD_ + t * 8 + qr;
        float v00 = o[t][0] * inv0, v01 = o[t][1] * inv0;
        float v10 = o[t][2] * inv1, v11 = o[t][3] * inv1;
        __nv_bfloat16 h00 = __float2bfloat16(v00), h01 = __float2bfloat16(v01);
        __nv_bfloat16 h10 = __float2bfloat16(v10), h11 = __float2bfloat16(v11);
        uint32_t hi0 = ((uint32_t)*(uint16_t*)&h01 << 16) | *(uint16_t*)&h00;
        uint32_t hi1 = ((uint32_t)*(uint16_t*)&h11 << 16) | *(uint16_t*)&h10;
        uint32_t lo0 = packbf(v00 - __bfloat162float(h00), v01 - __bfloat162float(h01));
        uint32_t lo1 = packbf(v10 - __bfloat162float(h10), v11 - __bfloat162float(h11));
        *(uint32_t*)(a3out + row0 + col)           = hi0;
        *(uint32_t*)(a3out + row0 + D_ + col)      = hi0;
        *(uint32_t*)(a3out + row0 + 2 * D_ + col)  = lo0;
        *(uint32_t*)(a3out + row1 + col)           = hi1;
        *(uint32_t*)(a3out + row1 + D_ + col)      = hi1;
        *(uint32_t*)(a3out + row1 + 2 * D_ + col)  = lo1;
    }
}

// ---------------------------------------------------------------------------
extern "C" void kernel_launch(void* const* d_in, const int* in_sizes, int n_in,
                              void* d_out, int out_size)
{
    const float* x     = (const float*)d_in[0];
    const float* Wqkv  = (const float*)d_in[1];
    const float* bqkv  = (const float*)d_in[2];
    const float* Wproj = (const float*)d_in[3];
    const float* bproj = (const float*)d_in[4];
    float* out = (float*)d_out;

    __nv_bfloat16 *a3, *b3, *kvh, *kvl;
    cudaGetSymbolAddress((void**)&a3, g_a3);
    cudaGetSymbolAddress((void**)&b3, g_b3);
    cudaGetSymbolAddress((void**)&kvh, g_kv_hi);
    cudaGetSymbolAddress((void**)&kvl, g_kv_lo);

    const int gemm_smem = NSTAGE * STG_BYTES;
    cudaFuncSetAttribute(gemm_bf16x3, cudaFuncAttributeMaxDynamicSharedMemorySize, gemm_smem);
    const int attn_smem = 8 * TEN * 2;   // 2 bufs x 4 tensors = 147456 B
    cudaFuncSetAttribute(attn_mma, cudaFuncAttributeMaxDynamicSharedMemorySize, attn_smem);

    const int convA_total = M_ * D_;

    // 1) qkv = x @ Wqkv + bqkv  -> bf16 hi/lo
    conv_a3<<<(convA_total + 255) / 256, 256>>>(x, a3, convA_total);
    conv_b3t<<<dim3(NQKV / 32, D_ / 32), dim3(32, 8)>>>(Wqkv, b3, NQKV);
    gemm_bf16x3<<<dim3(NQKV / BN, M_ / BM), 256, gemm_smem>>>(a3, b3, bqkv, nullptr, kvh, kvl, NQKV);

    // 2) attention -> a3 (proj input, [hi|hi|lo])
    attn_mma<<<dim3(S_ / 128, H_, B_), 256, attn_smem>>>(kvh, kvl, a3);

    // 3) out = att @ Wproj + bproj (fp32)
    conv_b3t<<<dim3(D_ / 32, D_ / 32), dim3(32, 8)>>>(Wproj, b3, D_);
    gemm_bf16x3<<<dim3(D_ / BN, M_ / BM), 256, gemm_smem>>>(a3, b3, bproj, out, nullptr, nullptr, D_);
}